// round 1
// baseline (speedup 1.0000x reference)
#include <cuda_runtime.h>
#include <math.h>

#define BB    16
#define NQ    256
#define NKV   2304
#define HDIM  768
#define IMGD  1024
#define HEADS 12
#define INTER 3072
#define ATTN_SCALE 0.125f

// ---------------- scratch (static __device__, allocation-free) ----------------
__device__ float g_xn [BB*NKV*IMGD];
__device__ float g_hn [BB*NQ*HDIM];
__device__ float g_q  [BB*NQ*HDIM];
__device__ float g_k  [BB*NKV*HDIM];
__device__ float g_v  [BB*NKV*HDIM];
__device__ float g_ctx[BB*NQ*HDIM];
__device__ float g_o1 [BB*NQ*HDIM];
__device__ float g_hnf[BB*NQ*HDIM];
__device__ float g_ff [BB*NQ*INTER];

// ---------------- LayerNorm ----------------
__device__ __forceinline__ float blk_sum(float v) {
    __shared__ float red[8];
    int lane = threadIdx.x & 31, wid = threadIdx.x >> 5;
#pragma unroll
    for (int m = 16; m; m >>= 1) v += __shfl_xor_sync(0xffffffffu, v, m);
    __syncthreads();               // protect red from previous use
    if (lane == 0) red[wid] = v;
    __syncthreads();
    float s = 0.f;
#pragma unroll
    for (int i = 0; i < 8; i++) s += red[i];
    return s;
}

__global__ void __launch_bounds__(256) ln_kernel(
    const float* __restrict__ in, const float* __restrict__ gam,
    const float* __restrict__ bet, float* __restrict__ out, int D)
{
    long row = blockIdx.x;
    const float* xr = in + row * (long)D;
    float xv[4];
    int n = 0; float s = 0.f;
    for (int i = threadIdx.x; i < D; i += 256) { float t = xr[i]; xv[n++] = t; s += t; }
    s = blk_sum(s);
    float mu = s / (float)D;
    float vr = 0.f;
    for (int c = 0; c < n; c++) { float d = xv[c] - mu; vr += d * d; }
    vr = blk_sum(vr);
    float rstd = rsqrtf(vr / (float)D + 1e-5f);
    float* orow = out + row * (long)D;
    n = 0;
    for (int i = threadIdx.x; i < D; i += 256)
        orow[i] = (xv[n++] - mu) * rstd * gam[i] + bet[i];
}

// ---------------- SGEMM: C[M,N] = A[M,K] @ W[K,N] + bias (+res | gelu) ----------------
// 128x128 tile, BK=8, 256 threads, 8x8 micro-tile, register prefetch pipeline.
// epi: 0 = bias only, 1 = bias + res, 2 = bias + exact GELU
__global__ void __launch_bounds__(256) gemm128(
    const float* __restrict__ A, const float* __restrict__ W,
    const float* __restrict__ bias, const float* __restrict__ res,
    float* __restrict__ C, int M, int N, int K, int epi)
{
    __shared__ __align__(16) float As[8][132];   // k-major, padded: conflict-free T-store
    __shared__ __align__(16) float Ws[8][128];
    int t  = threadIdx.x;
    int tx = t & 15, ty = t >> 4;
    int m0 = blockIdx.y * 128, n0 = blockIdx.x * 128;

    int arow = t >> 1,  akc  = (t & 1) * 4;      // A: 128 rows x 8 k
    int wrow = t >> 5,  wcol = (t & 31) * 4;     // W: 8 rows x 128 n
    const float* Ap = A + (long)(m0 + arow) * K + akc;
    const float* Wp = W + (long)wrow * N + n0 + wcol;

    float4 aR = *(const float4*)Ap;
    float4 wR = *(const float4*)Wp;

    float acc[8][8];
#pragma unroll
    for (int i = 0; i < 8; i++)
#pragma unroll
        for (int j = 0; j < 8; j++) acc[i][j] = 0.f;

    for (int k0 = 0; k0 < K; k0 += 8) {
        As[akc + 0][arow] = aR.x; As[akc + 1][arow] = aR.y;
        As[akc + 2][arow] = aR.z; As[akc + 3][arow] = aR.w;
        *(float4*)&Ws[wrow][wcol] = wR;
        __syncthreads();
        if (k0 + 8 < K) {                       // prefetch next tile into regs
            aR = *(const float4*)(Ap + k0 + 8);
            wR = *(const float4*)(Wp + (long)(k0 + 8) * N);
        }
#pragma unroll
        for (int kk = 0; kk < 8; kk++) {
            float4 a0 = *(const float4*)&As[kk][ty * 4];
            float4 a1 = *(const float4*)&As[kk][64 + ty * 4];
            float4 w0 = *(const float4*)&Ws[kk][tx * 4];
            float4 w1 = *(const float4*)&Ws[kk][64 + tx * 4];
            float af[8] = {a0.x,a0.y,a0.z,a0.w,a1.x,a1.y,a1.z,a1.w};
            float wf[8] = {w0.x,w0.y,w0.z,w0.w,w1.x,w1.y,w1.z,w1.w};
#pragma unroll
            for (int i = 0; i < 8; i++)
#pragma unroll
                for (int j = 0; j < 8; j++) acc[i][j] += af[i] * wf[j];
        }
        __syncthreads();
    }

#pragma unroll
    for (int ih = 0; ih < 2; ih++)
#pragma unroll
    for (int ii = 0; ii < 4; ii++) {
        int  i = ih * 4 + ii;
        long r = m0 + ih * 64 + ty * 4 + ii;
#pragma unroll
        for (int jh = 0; jh < 2; jh++) {
            int c = n0 + jh * 64 + tx * 4;
            float4 v; float* vv = (float*)&v;
#pragma unroll
            for (int j = 0; j < 4; j++) {
                float xr2 = acc[i][jh * 4 + j] + bias[c + j];
                if (epi == 1)      xr2 += res[r * (long)N + c + j];
                else if (epi == 2) xr2 = 0.5f * xr2 * (1.f + erff(xr2 * 0.70710678118654752f));
                vv[j] = xr2;
            }
            *(float4*)&C[r * (long)N + c] = v;
        }
    }
}

// ---------------- Flash attention (fp32, online softmax) ----------------
// Block: 64 q-rows of one (b,h). 256 threads (16x16). Head dim 64. KV tiles of 64.
// Natural-layout smem (stride 68) + strided column mapping => conflict-light.
__global__ void __launch_bounds__(256) attn_kernel(
    const float* __restrict__ Q, const float* __restrict__ K,
    const float* __restrict__ V, float* __restrict__ O)
{
    extern __shared__ float smf[];
    float* qs = smf;                 // [64][68]
    float* ks = smf + 64 * 68;       // [64][68]
    float* vs = smf + 2 * 64 * 68;   // [64][68]
    float* ps = smf + 3 * 64 * 68;   // [64][68]
    int t  = threadIdx.x, tx = t & 15, ty = t >> 4;
    int qb = blockIdx.x, h = blockIdx.y, b = blockIdx.z;

    const float* Qb = Q + ((long)b * NQ + qb * 64) * HDIM + h * 64;
    const float* Kb = K + (long)b * NKV * HDIM + h * 64;
    const float* Vb = V + (long)b * NKV * HDIM + h * 64;

#pragma unroll
    for (int i = 0; i < 4; i++) {
        int idx = t + i * 256;
        int r = idx >> 4, c4 = (idx & 15) * 4;
        *(float4*)&qs[r * 68 + c4] = *(const float4*)&Qb[(long)r * HDIM + c4];
    }
    float m[4], l[4], o[4][4];
#pragma unroll
    for (int i = 0; i < 4; i++) {
        m[i] = -3.4e38f; l[i] = 0.f;
#pragma unroll
        for (int j = 0; j < 4; j++) o[i][j] = 0.f;
    }
    __syncthreads();

    for (int j0 = 0; j0 < NKV; j0 += 64) {
#pragma unroll
        for (int i = 0; i < 4; i++) {
            int idx = t + i * 256;
            int r = idx >> 4, c4 = (idx & 15) * 4;
            *(float4*)&ks[r * 68 + c4] = *(const float4*)&Kb[(long)(j0 + r) * HDIM + c4];
            *(float4*)&vs[r * 68 + c4] = *(const float4*)&Vb[(long)(j0 + r) * HDIM + c4];
        }
        __syncthreads();

        float s[4][4];
#pragma unroll
        for (int i = 0; i < 4; i++)
#pragma unroll
            for (int j = 0; j < 4; j++) s[i][j] = 0.f;
#pragma unroll
        for (int kc = 0; kc < 16; kc++) {
            float4 a[4], w[4];
#pragma unroll
            for (int i = 0; i < 4; i++)
                a[i] = *(const float4*)&qs[(ty * 4 + i) * 68 + kc * 4];
#pragma unroll
            for (int jj = 0; jj < 4; jj++)
                w[jj] = *(const float4*)&ks[(tx + 16 * jj) * 68 + kc * 4];
#pragma unroll
            for (int i = 0; i < 4; i++)
#pragma unroll
                for (int jj = 0; jj < 4; jj++)
                    s[i][jj] += a[i].x * w[jj].x + a[i].y * w[jj].y +
                                a[i].z * w[jj].z + a[i].w * w[jj].w;
        }

        // online softmax over the 16-lane row group (lanes 0-15 / 16-31 per warp)
#pragma unroll
        for (int i = 0; i < 4; i++) {
#pragma unroll
            for (int jj = 0; jj < 4; jj++) s[i][jj] *= ATTN_SCALE;
            float tm = fmaxf(fmaxf(s[i][0], s[i][1]), fmaxf(s[i][2], s[i][3]));
#pragma unroll
            for (int d = 8; d; d >>= 1) tm = fmaxf(tm, __shfl_xor_sync(0xffffffffu, tm, d));
            float nm   = fmaxf(m[i], tm);
            float corr = __expf(m[i] - nm);
            float psum = 0.f;
#pragma unroll
            for (int jj = 0; jj < 4; jj++) {
                float p = __expf(s[i][jj] - nm);
                ps[(ty * 4 + i) * 68 + tx + 16 * jj] = p;
                psum += p;
            }
#pragma unroll
            for (int d = 8; d; d >>= 1) psum += __shfl_xor_sync(0xffffffffu, psum, d);
            l[i] = l[i] * corr + psum;
            m[i] = nm;
#pragma unroll
            for (int jj = 0; jj < 4; jj++) o[i][jj] *= corr;
        }
        __syncthreads();

        // o += P @ V
#pragma unroll
        for (int jb = 0; jb < 16; jb++) {
            float pa[4][4];
#pragma unroll
            for (int i = 0; i < 4; i++)
                *(float4*)pa[i] = *(const float4*)&ps[(ty * 4 + i) * 68 + jb * 4];
#pragma unroll
            for (int j2 = 0; j2 < 4; j2++) {
                int j = jb * 4 + j2;
                float vv[4];
#pragma unroll
                for (int jj = 0; jj < 4; jj++) vv[jj] = vs[j * 68 + tx + 16 * jj];
#pragma unroll
                for (int i = 0; i < 4; i++)
#pragma unroll
                    for (int jj = 0; jj < 4; jj++) o[i][jj] += pa[i][j2] * vv[jj];
            }
        }
        __syncthreads();
    }

    float* Ob = O + ((long)b * NQ + qb * 64) * HDIM + h * 64;
#pragma unroll
    for (int i = 0; i < 4; i++) {
        float inv = 1.f / l[i];
#pragma unroll
        for (int jj = 0; jj < 4; jj++)
            Ob[(long)(ty * 4 + i) * HDIM + tx + 16 * jj] = o[i][jj] * inv;
    }
}

// ---------------- launcher ----------------
extern "C" void kernel_launch(void* const* d_in, const int* in_sizes, int n_in,
                              void* d_out, int out_size)
{
    const float* hid = (const float*)d_in[0];
    const float* x   = (const float*)d_in[1];
    const float* Wq  = (const float*)d_in[2];
    const float* bq  = (const float*)d_in[3];
    const float* Wk  = (const float*)d_in[4];
    const float* bk  = (const float*)d_in[5];
    const float* Wv  = (const float*)d_in[6];
    const float* bv  = (const float*)d_in[7];
    const float* Wo  = (const float*)d_in[8];
    const float* bo  = (const float*)d_in[9];
    const float* W1  = (const float*)d_in[10];
    const float* b1  = (const float*)d_in[11];
    const float* W2  = (const float*)d_in[12];
    const float* b2  = (const float*)d_in[13];
    const float* gi  = (const float*)d_in[14];
    const float* bi  = (const float*)d_in[15];
    const float* gh  = (const float*)d_in[16];
    const float* bh  = (const float*)d_in[17];
    const float* gf  = (const float*)d_in[18];
    const float* bf  = (const float*)d_in[19];

    float *xn, *hn, *q, *k, *v, *ctx, *o1, *hnf, *ff;
    cudaGetSymbolAddress((void**)&xn,  g_xn);
    cudaGetSymbolAddress((void**)&hn,  g_hn);
    cudaGetSymbolAddress((void**)&q,   g_q);
    cudaGetSymbolAddress((void**)&k,   g_k);
    cudaGetSymbolAddress((void**)&v,   g_v);
    cudaGetSymbolAddress((void**)&ctx, g_ctx);
    cudaGetSymbolAddress((void**)&o1,  g_o1);
    cudaGetSymbolAddress((void**)&hnf, g_hnf);
    cudaGetSymbolAddress((void**)&ff,  g_ff);

    const int ASMEM = 4 * 64 * 68 * 4;   // 69632 B
    cudaFuncSetAttribute(attn_kernel, cudaFuncAttributeMaxDynamicSharedMemorySize, ASMEM);

    // 1) LayerNorms of inputs
    ln_kernel<<<BB * NKV, 256>>>(x,   gi, bi, xn, IMGD);
    ln_kernel<<<BB * NQ,  256>>>(hid, gh, bh, hn, HDIM);

    // 2) Q/K/V projections
    gemm128<<<dim3(HDIM / 128, BB * NQ  / 128), 256>>>(hn, Wq, bq, nullptr, q, BB * NQ,  HDIM, HDIM, 0);
    gemm128<<<dim3(HDIM / 128, BB * NKV / 128), 256>>>(xn, Wk, bk, nullptr, k, BB * NKV, HDIM, IMGD, 0);
    gemm128<<<dim3(HDIM / 128, BB * NKV / 128), 256>>>(xn, Wv, bv, nullptr, v, BB * NKV, HDIM, IMGD, 0);

    // 3) attention
    attn_kernel<<<dim3(NQ / 64, HEADS, BB), 256, ASMEM>>>(q, k, v, ctx);

    // 4) output proj + residual
    gemm128<<<dim3(HDIM / 128, BB * NQ / 128), 256>>>(ctx, Wo, bo, hid, o1, BB * NQ, HDIM, HDIM, 1);

    // 5) FFN
    ln_kernel<<<BB * NQ, 256>>>(o1, gf, bf, hnf, HDIM);
    gemm128<<<dim3(INTER / 128, BB * NQ / 128), 256>>>(hnf, W1, b1, nullptr, ff, BB * NQ, INTER, HDIM, 2);
    gemm128<<<dim3(HDIM / 128, BB * NQ / 128), 256>>>(ff, W2, b2, o1, (float*)d_out, BB * NQ, HDIM, INTER, 1);
}

// round 3
// speedup vs baseline: 1.9461x; 1.9461x over previous
#include <cuda_runtime.h>
#include <cstdint>
#include <math.h>

#define BB    16
#define NQ    256
#define NKV   2304
#define HDIM  768
#define IMGD  1024
#define HEADS 12
#define INTER 3072
#define ATTN_SCALE 0.125f

// ---------------- scratch (static __device__, allocation-free) ----------------
__device__ float g_xn [BB*NKV*IMGD];
__device__ float g_hn [BB*NQ*HDIM];
__device__ float g_q  [BB*NQ*HDIM];
__device__ float g_k  [BB*NKV*HDIM];
__device__ float g_v  [BB*NKV*HDIM];
__device__ float g_ctx[BB*NQ*HDIM];
__device__ float g_o1 [BB*NQ*HDIM];
__device__ float g_hnf[BB*NQ*HDIM];
__device__ float g_ff [BB*NQ*INTER];
// tf32-rounded weights (same [K,N] layout as input)
__device__ float g_wq[HDIM*HDIM];
__device__ float g_wk[IMGD*HDIM];
__device__ float g_wv[IMGD*HDIM];
__device__ float g_wo[HDIM*HDIM];
__device__ float g_w1[HDIM*INTER];
__device__ float g_w2[INTER*HDIM];

// ---------------- helpers ----------------
__device__ __forceinline__ uint32_t smem_u32(const void* p) {
    uint32_t a;
    asm("{ .reg .u64 t; cvta.to.shared.u64 t, %1; cvt.u32.u64 %0, t; }" : "=r"(a) : "l"(p));
    return a;
}
__device__ __forceinline__ float tf32r(float x) {
    uint32_t u; asm("cvt.rna.tf32.f32 %0, %1;" : "=r"(u) : "f"(x));
    return __uint_as_float(u);
}
__device__ __forceinline__ void cpa16(uint32_t dst, const void* src) {
    asm volatile("cp.async.cg.shared.global [%0], [%1], 16;\n" :: "r"(dst), "l"(src));
}
__device__ __forceinline__ void mma_tf32(float* c, const uint32_t* a, const uint32_t* b) {
    asm volatile(
        "mma.sync.aligned.m16n8k8.row.col.f32.tf32.tf32.f32 "
        "{%0,%1,%2,%3}, {%4,%5,%6,%7}, {%8,%9}, {%0,%1,%2,%3};\n"
        : "+f"(c[0]), "+f"(c[1]), "+f"(c[2]), "+f"(c[3])
        : "r"(a[0]), "r"(a[1]), "r"(a[2]), "r"(a[3]), "r"(b[0]), "r"(b[1]));
}

// ---------------- weight rounding (rna -> tf32) ----------------
__global__ void __launch_bounds__(256) wround(const float* __restrict__ W,
                                              float* __restrict__ O, int n) {
    int i = blockIdx.x * 1024 + threadIdx.x * 4;
    if (i < n) {
        float4 v = *(const float4*)(W + i);
        v.x = tf32r(v.x); v.y = tf32r(v.y); v.z = tf32r(v.z); v.w = tf32r(v.w);
        *(float4*)(O + i) = v;
    }
}

// ---------------- LayerNorm (tf32-rounded output; feeds GEMM A operands) ------
__device__ __forceinline__ float blk_sum(float v) {
    __shared__ float red[8];
    int lane = threadIdx.x & 31, wid = threadIdx.x >> 5;
#pragma unroll
    for (int m = 16; m; m >>= 1) v += __shfl_xor_sync(0xffffffffu, v, m);
    __syncthreads();
    if (lane == 0) red[wid] = v;
    __syncthreads();
    float s = 0.f;
#pragma unroll
    for (int i = 0; i < 8; i++) s += red[i];
    return s;
}

__global__ void __launch_bounds__(256) ln_kernel(
    const float* __restrict__ in, const float* __restrict__ gam,
    const float* __restrict__ bet, float* __restrict__ out, int D)
{
    long row = blockIdx.x;
    const float* xr = in + row * (long)D;
    float xv[4];
    int n = 0; float s = 0.f;
    for (int i = threadIdx.x; i < D; i += 256) { float t = xr[i]; xv[n++] = t; s += t; }
    s = blk_sum(s);
    float mu = s / (float)D;
    float vr = 0.f;
    for (int c = 0; c < n; c++) { float d = xv[c] - mu; vr += d * d; }
    vr = blk_sum(vr);
    float rstd = rsqrtf(vr / (float)D + 1e-5f);
    float* orow = out + row * (long)D;
    n = 0;
    for (int i = threadIdx.x; i < D; i += 256)
        orow[i] = tf32r((xv[n++] - mu) * rstd * gam[i] + bet[i]);
}

// ---------------- tf32 mma.sync GEMM ----------------
// C[M,N] = A[M,K] @ W[K,N] + bias (+res | gelu->tf32)
// CTA 128x128, BK=32, 256 threads, 8 warps 2(m)x4(n), warp tile 64x32.
// 3-stage cp.async pipeline.
#define GAS_F (128*36)          // A stage floats (padded rows of 36)
#define GBS_F (32*132)          // B stage floats (padded rows of 132)
#define GST_F (GAS_F + GBS_F)   // 8832 floats = 35328 B
#define GSMEM (3 * GST_F * 4)   // 105984 B

__global__ void __launch_bounds__(256, 2) gemm_mma(
    const float* __restrict__ A, const float* __restrict__ Bw,
    const float* __restrict__ bias, const float* __restrict__ res,
    float* __restrict__ C, int M, int N, int K, int epi)
{
    extern __shared__ float smf[];
    int tid = threadIdx.x, lane = tid & 31, wid = tid >> 5;
    int gid = lane >> 2, tig = lane & 3;
    int wm = wid & 1, wn = wid >> 1;            // warp tile origin: (wm*64, wn*32)
    int m0 = blockIdx.y * 128, n0 = blockIdx.x * 128;

    float acc[4][4][4];
#pragma unroll
    for (int i = 0; i < 4; i++)
#pragma unroll
        for (int j = 0; j < 4; j++)
#pragma unroll
            for (int r = 0; r < 4; r++) acc[i][j][r] = 0.f;

    const int NC = K / 32;

    auto issue = [&](int c, int s) {
        float* as = smf + s * GST_F;
        float* bs = as + GAS_F;
        long kb = (long)c * 32;
#pragma unroll
        for (int i = 0; i < 4; i++) {
            int idx = tid + i * 256;
            int r = idx >> 3, kc = (idx & 7) * 4;
            cpa16(smem_u32(as + r * 36 + kc), A + (long)(m0 + r) * K + kb + kc);
        }
#pragma unroll
        for (int i = 0; i < 4; i++) {
            int idx = tid + i * 256;
            int r = idx >> 5, nc = (idx & 31) * 4;
            cpa16(smem_u32(bs + r * 132 + nc), Bw + (kb + r) * (long)N + n0 + nc);
        }
        asm volatile("cp.async.commit_group;\n" ::: "memory");
    };

    issue(0, 0);
    if (NC > 1) issue(1, 1);

    for (int c = 0; c < NC; c++) {
        int s = c % 3;
        if (c + 1 < NC) asm volatile("cp.async.wait_group 1;\n" ::: "memory");
        else            asm volatile("cp.async.wait_group 0;\n" ::: "memory");
        __syncthreads();

        const float* as = smf + s * GST_F;
        const float* bs = as + GAS_F;
#pragma unroll
        for (int kk = 0; kk < 4; kk++) {
            int k0 = kk * 8;
            uint32_t a[4][4], b[4][2];
#pragma unroll
            for (int mf = 0; mf < 4; mf++) {
                const float* ap = as + (wm * 64 + mf * 16 + gid) * 36 + k0 + tig;
                a[mf][0] = __float_as_uint(ap[0]);
                a[mf][1] = __float_as_uint(ap[8 * 36]);
                a[mf][2] = __float_as_uint(ap[4]);
                a[mf][3] = __float_as_uint(ap[8 * 36 + 4]);
            }
#pragma unroll
            for (int nf = 0; nf < 4; nf++) {
                const float* bp = bs + (k0 + tig) * 132 + wn * 32 + nf * 8 + gid;
                b[nf][0] = __float_as_uint(bp[0]);
                b[nf][1] = __float_as_uint(bp[4 * 132]);
            }
#pragma unroll
            for (int mf = 0; mf < 4; mf++)
#pragma unroll
                for (int nf = 0; nf < 4; nf++)
                    mma_tf32(acc[mf][nf], a[mf], b[nf]);
        }
        __syncthreads();
        if (c + 2 < NC) issue(c + 2, (c + 2) % 3);
    }

    // ---- epilogue ----
    int cbase = n0 + wn * 32 + 2 * tig;
    float2 bl[4];
#pragma unroll
    for (int nf = 0; nf < 4; nf++)
        bl[nf] = *(const float2*)(bias + cbase + nf * 8);

#pragma unroll
    for (int mf = 0; mf < 4; mf++) {
#pragma unroll
        for (int half = 0; half < 2; half++) {
            long r = m0 + wm * 64 + mf * 16 + gid + half * 8;
#pragma unroll
            for (int nf = 0; nf < 4; nf++) {
                int col = cbase + nf * 8;
                float v0 = acc[mf][nf][half * 2 + 0] + bl[nf].x;
                float v1 = acc[mf][nf][half * 2 + 1] + bl[nf].y;
                if (epi == 1) {
                    float2 rv = *(const float2*)(res + r * (long)N + col);
                    v0 += rv.x; v1 += rv.y;
                } else if (epi == 2) {
                    v0 = tf32r(0.5f * v0 * (1.f + erff(v0 * 0.70710678118654752f)));
                    v1 = tf32r(0.5f * v1 * (1.f + erff(v1 * 0.70710678118654752f)));
                }
                *(float2*)(C + r * (long)N + col) = make_float2(v0, v1);
            }
        }
    }
}

// ---------------- Flash attention (fp32, online softmax) ----------------
__global__ void __launch_bounds__(256) attn_kernel(
    const float* __restrict__ Q, const float* __restrict__ K,
    const float* __restrict__ V, float* __restrict__ O)
{
    extern __shared__ float smf[];
    float* qs = smf;                 // [64][68]
    float* ks = smf + 64 * 68;
    float* vs = smf + 2 * 64 * 68;
    float* ps = smf + 3 * 64 * 68;
    int t  = threadIdx.x, tx = t & 15, ty = t >> 4;
    int qb = blockIdx.x, h = blockIdx.y, b = blockIdx.z;

    const float* Qb = Q + ((long)b * NQ + qb * 64) * HDIM + h * 64;
    const float* Kb = K + (long)b * NKV * HDIM + h * 64;
    const float* Vb = V + (long)b * NKV * HDIM + h * 64;

#pragma unroll
    for (int i = 0; i < 4; i++) {
        int idx = t + i * 256;
        int r = idx >> 4, c4 = (idx & 15) * 4;
        *(float4*)&qs[r * 68 + c4] = *(const float4*)&Qb[(long)r * HDIM + c4];
    }
    float m[4], l[4], o[4][4];
#pragma unroll
    for (int i = 0; i < 4; i++) {
        m[i] = -3.4e38f; l[i] = 0.f;
#pragma unroll
        for (int j = 0; j < 4; j++) o[i][j] = 0.f;
    }
    __syncthreads();

    for (int j0 = 0; j0 < NKV; j0 += 64) {
#pragma unroll
        for (int i = 0; i < 4; i++) {
            int idx = t + i * 256;
            int r = idx >> 4, c4 = (idx & 15) * 4;
            *(float4*)&ks[r * 68 + c4] = *(const float4*)&Kb[(long)(j0 + r) * HDIM + c4];
            *(float4*)&vs[r * 68 + c4] = *(const float4*)&Vb[(long)(j0 + r) * HDIM + c4];
        }
        __syncthreads();

        float s[4][4];
#pragma unroll
        for (int i = 0; i < 4; i++)
#pragma unroll
            for (int j = 0; j < 4; j++) s[i][j] = 0.f;
#pragma unroll
        for (int kc = 0; kc < 16; kc++) {
            float4 a[4], w[4];
#pragma unroll
            for (int i = 0; i < 4; i++)
                a[i] = *(const float4*)&qs[(ty * 4 + i) * 68 + kc * 4];
#pragma unroll
            for (int jj = 0; jj < 4; jj++)
                w[jj] = *(const float4*)&ks[(tx + 16 * jj) * 68 + kc * 4];
#pragma unroll
            for (int i = 0; i < 4; i++)
#pragma unroll
                for (int jj = 0; jj < 4; jj++)
                    s[i][jj] += a[i].x * w[jj].x + a[i].y * w[jj].y +
                                a[i].z * w[jj].z + a[i].w * w[jj].w;
        }

#pragma unroll
        for (int i = 0; i < 4; i++) {
#pragma unroll
            for (int jj = 0; jj < 4; jj++) s[i][jj] *= ATTN_SCALE;
            float tm = fmaxf(fmaxf(s[i][0], s[i][1]), fmaxf(s[i][2], s[i][3]));
#pragma unroll
            for (int d = 8; d; d >>= 1) tm = fmaxf(tm, __shfl_xor_sync(0xffffffffu, tm, d));
            float nm   = fmaxf(m[i], tm);
            float corr = __expf(m[i] - nm);
            float psum = 0.f;
#pragma unroll
            for (int jj = 0; jj < 4; jj++) {
                float p = __expf(s[i][jj] - nm);
                ps[(ty * 4 + i) * 68 + tx + 16 * jj] = p;
                psum += p;
            }
#pragma unroll
            for (int d = 8; d; d >>= 1) psum += __shfl_xor_sync(0xffffffffu, psum, d);
            l[i] = l[i] * corr + psum;
            m[i] = nm;
#pragma unroll
            for (int jj = 0; jj < 4; jj++) o[i][jj] *= corr;
        }
        __syncthreads();

#pragma unroll
        for (int jb = 0; jb < 16; jb++) {
            float pa[4][4];
#pragma unroll
            for (int i = 0; i < 4; i++)
                *(float4*)pa[i] = *(const float4*)&ps[(ty * 4 + i) * 68 + jb * 4];
#pragma unroll
            for (int j2 = 0; j2 < 4; j2++) {
                int j = jb * 4 + j2;
                float vv[4];
#pragma unroll
                for (int jj = 0; jj < 4; jj++) vv[jj] = vs[j * 68 + tx + 16 * jj];
#pragma unroll
                for (int i = 0; i < 4; i++)
#pragma unroll
                    for (int jj = 0; jj < 4; jj++) o[i][jj] += pa[i][j2] * vv[jj];
            }
        }
        __syncthreads();
    }

    float* Ob = O + ((long)b * NQ + qb * 64) * HDIM + h * 64;
#pragma unroll
    for (int i = 0; i < 4; i++) {
        float inv = 1.f / l[i];
#pragma unroll
        for (int jj = 0; jj < 4; jj++)
            Ob[(long)(ty * 4 + i) * HDIM + tx + 16 * jj] = tf32r(o[i][jj] * inv);
    }
}

// ---------------- launcher ----------------
extern "C" void kernel_launch(void* const* d_in, const int* in_sizes, int n_in,
                              void* d_out, int out_size)
{
    const float* hid = (const float*)d_in[0];
    const float* x   = (const float*)d_in[1];
    const float* Wq  = (const float*)d_in[2];
    const float* bq  = (const float*)d_in[3];
    const float* Wk  = (const float*)d_in[4];
    const float* bk  = (const float*)d_in[5];
    const float* Wv  = (const float*)d_in[6];
    const float* bv  = (const float*)d_in[7];
    const float* Wo  = (const float*)d_in[8];
    const float* bo  = (const float*)d_in[9];
    const float* W1  = (const float*)d_in[10];
    const float* b1  = (const float*)d_in[11];
    const float* W2  = (const float*)d_in[12];
    const float* b2  = (const float*)d_in[13];
    const float* gi  = (const float*)d_in[14];
    const float* bi  = (const float*)d_in[15];
    const float* gh  = (const float*)d_in[16];
    const float* bh  = (const float*)d_in[17];
    const float* gf  = (const float*)d_in[18];
    const float* bf  = (const float*)d_in[19];

    float *xn, *hn, *q, *k, *v, *ctx, *o1, *hnf, *ff;
    float *wq, *wk, *wv, *wo, *w1, *w2;
    cudaGetSymbolAddress((void**)&xn,  g_xn);
    cudaGetSymbolAddress((void**)&hn,  g_hn);
    cudaGetSymbolAddress((void**)&q,   g_q);
    cudaGetSymbolAddress((void**)&k,   g_k);
    cudaGetSymbolAddress((void**)&v,   g_v);
    cudaGetSymbolAddress((void**)&ctx, g_ctx);
    cudaGetSymbolAddress((void**)&o1,  g_o1);
    cudaGetSymbolAddress((void**)&hnf, g_hnf);
    cudaGetSymbolAddress((void**)&ff,  g_ff);
    cudaGetSymbolAddress((void**)&wq,  g_wq);
    cudaGetSymbolAddress((void**)&wk,  g_wk);
    cudaGetSymbolAddress((void**)&wv,  g_wv);
    cudaGetSymbolAddress((void**)&wo,  g_wo);
    cudaGetSymbolAddress((void**)&w1,  g_w1);
    cudaGetSymbolAddress((void**)&w2,  g_w2);

    const int ASMEM = 4 * 64 * 68 * 4;
    cudaFuncSetAttribute(attn_kernel, cudaFuncAttributeMaxDynamicSharedMemorySize, ASMEM);
    cudaFuncSetAttribute(gemm_mma,    cudaFuncAttributeMaxDynamicSharedMemorySize, GSMEM);

    // 0) weight rounding (rna -> tf32)
    wround<<<(HDIM * HDIM  + 1023) / 1024, 256>>>(Wq, wq, HDIM * HDIM);
    wround<<<(IMGD * HDIM  + 1023) / 1024, 256>>>(Wk, wk, IMGD * HDIM);
    wround<<<(IMGD * HDIM  + 1023) / 1024, 256>>>(Wv, wv, IMGD * HDIM);
    wround<<<(HDIM * HDIM  + 1023) / 1024, 256>>>(Wo, wo, HDIM * HDIM);
    wround<<<(HDIM * INTER + 1023) / 1024, 256>>>(W1, w1, HDIM * INTER);
    wround<<<(INTER * HDIM + 1023) / 1024, 256>>>(W2, w2, INTER * HDIM);

    // 1) LayerNorms of inputs (tf32-rounded outputs)
    ln_kernel<<<BB * NKV, 256>>>(x,   gi, bi, xn, IMGD);
    ln_kernel<<<BB * NQ,  256>>>(hid, gh, bh, hn, HDIM);

    // 2) Q/K/V projections (tensor cores, tf32)
    gemm_mma<<<dim3(HDIM / 128, BB * NQ  / 128), 256, GSMEM>>>(hn, wq, bq, nullptr, q, BB * NQ,  HDIM, HDIM, 0);
    gemm_mma<<<dim3(HDIM / 128, BB * NKV / 128), 256, GSMEM>>>(xn, wk, bk, nullptr, k, BB * NKV, HDIM, IMGD, 0);
    gemm_mma<<<dim3(HDIM / 128, BB * NKV / 128), 256, GSMEM>>>(xn, wv, bv, nullptr, v, BB * NKV, HDIM, IMGD, 0);

    // 3) attention
    attn_kernel<<<dim3(NQ / 64, HEADS, BB), 256, ASMEM>>>(q, k, v, ctx);

    // 4) output proj + residual
    gemm_mma<<<dim3(HDIM / 128, BB * NQ / 128), 256, GSMEM>>>(ctx, wo, bo, hid, o1, BB * NQ, HDIM, HDIM, 1);

    // 5) FFN
    ln_kernel<<<BB * NQ, 256>>>(o1, gf, bf, hnf, HDIM);
    gemm_mma<<<dim3(INTER / 128, BB * NQ / 128), 256, GSMEM>>>(hnf, w1, b1, nullptr, ff, BB * NQ, INTER, HDIM, 2);
    gemm_mma<<<dim3(HDIM / 128,  BB * NQ / 128), 256, GSMEM>>>(ff, w2, b2, o1, (float*)d_out, BB * NQ, HDIM, INTER, 1);
}